// round 16
// baseline (speedup 1.0000x reference)
#include <cuda_runtime.h>
#include <cuda_fp16.h>
#include <cstdint>

// MeshConv via mma.sync (HMMA) fp16, split on B (W = Whi + Wlo), A = fp16(g).
// R15: bhi W-fragments in registers (h-invariant), blo as one 2-nt LDS.128/(h,s);
// staging loop warp-per-plane (no IDIV). mma-phase L1 wf: 1600 -> 1200 per tile.

#define F_DIM  500000
#define FO     499996
#define TILE_F 128
#define NTILES 3907
#define NTHR   128
#define GR     132
#define ROWB   48                 // gpack row bytes (8 ci-pair words + pad)
#define PLANE  (GR*ROWB)          // 6336 B per h
#define OFF_RAW (5*PLANE)         // 31680: raw x staging / blo table overlay
#define RAWSTR 2656               // raw plane stride (2640 + 16 pad)
#define SMEM_BYTES (OFF_RAW + 4*RAWSTR)   // 42304

typedef unsigned int u32;

__device__ __forceinline__ void mma16816(float* c, const u32* a, u32 b0, u32 b1) {
    asm volatile("mma.sync.aligned.m16n8k16.row.col.f32.f16.f16.f32 "
        "{%0,%1,%2,%3}, {%4,%5,%6,%7}, {%8,%9}, {%0,%1,%2,%3};"
        : "+f"(c[0]), "+f"(c[1]), "+f"(c[2]), "+f"(c[3])
        : "r"(a[0]), "r"(a[1]), "r"(a[2]), "r"(a[3]), "r"(b0), "r"(b1));
}
__device__ __forceinline__ void ldmx4(u32* r, u32 addr) {
    asm volatile("ldmatrix.sync.aligned.m8n8.x4.shared.b16 {%0,%1,%2,%3}, [%4];"
        : "=r"(r[0]), "=r"(r[1]), "=r"(r[2]), "=r"(r[3]) : "r"(addr));
}
__device__ __forceinline__ void lds128(u32* r, u32 addr) {
    asm volatile("ld.shared.v4.b32 {%0,%1,%2,%3}, [%4];"
        : "=r"(r[0]), "=r"(r[1]), "=r"(r[2]), "=r"(r[3]) : "r"(addr));
}
__device__ __forceinline__ u32 packh(float a, float bq) {   // {lo=a, hi=bq}
    return (u32)__half_as_ushort(__float2half(a))
         | ((u32)__half_as_ushort(__float2half(bq)) << 16);
}

extern __shared__ unsigned char smem[];

__global__ __launch_bounds__(NTHR, 5)
void meshconv_mma(const float* __restrict__ x, const float* __restrict__ W,
                  const float* __restrict__ b, float* __restrict__ y)
{
    const int tid  = threadIdx.x;
    const int wid  = tid >> 5, lane = tid & 31;
    const int grp  = lane >> 2, tg = lane & 3;
    const int n    = blockIdx.y;
    const int f0   = blockIdx.x * TILE_F;
    const u32 sbase = (u32)__cvta_generic_to_shared(smem);

    // valid bytes in a 2640B ci-slice starting at f0 (tail zero-filled)
    long long vbl = ((long long)F_DIM - f0) * 20;
    int vb = vbl > GR*20 ? GR*20 : (int)vbl;

    const char* xb = (const char*)x;

    // ==== staging + gpack build, 4 chunks of 4 ci planes (warp-per-plane) ====
    for (int c = 0; c < 4; ++c) {
        // coalesced 16B cp.async: warp wid stages plane wid of this chunk
        {
            const char* src0 = xb + ((size_t)(n*16 + 4*c + wid))*F_DIM*20 + (size_t)f0*20;
            u32 dst0 = sbase + OFF_RAW + wid*RAWSTR;
            #pragma unroll
            for (int j = 0; j < 6; ++j) {
                int i = lane + 32*j;
                if (i < 165) {
                    int ob = i * 16;
                    int sz = vb - ob; sz = sz < 0 ? 0 : (sz > 16 ? 16 : sz);
                    asm volatile("cp.async.ca.shared.global [%0], [%1], 16, %2;"
                                 :: "r"(dst0 + ob), "l"(src0 + (sz ? ob : 0)), "r"(sz)
                                 : "memory");
                }
            }
        }
        asm volatile("cp.async.commit_group;" ::: "memory");
        asm volatile("cp.async.wait_group 0;" ::: "memory");
        __syncthreads();

        // g-compute: thread = (r, ci-pair within chunk); bank-perfect raw LDS
        {
            const int rl = lane & 15, cpl = lane >> 4;
            const int cp = 2*c + cpl;
            for (int rb = wid*16; rb < GR; rb += 64) {
                int r = rb + rl;
                if (r < GR) {
                    const float* pa = (const float*)(smem + OFF_RAW + (2*cpl  )*RAWSTR + r*20);
                    const float* pb = (const float*)(smem + OFF_RAW + (2*cpl+1)*RAWSTR + r*20);
                    float a0=pa[0], a1=pa[1], a2=pa[2], a3=pa[3], a4=pa[4];
                    float c0=pb[0], c1=pb[1], c2=pb[2], c3=pb[3], c4=pb[4];
                    float gA[5], gB[5];
                    gA[0]=a0; gA[1]=a1+a3; gA[2]=a2+a4; gA[3]=fabsf(a1-a3); gA[4]=fabsf(a2-a4);
                    gB[0]=c0; gB[1]=c1+c3; gB[2]=c2+c4; gB[3]=fabsf(c1-c3); gB[4]=fabsf(c2-c4);
                    #pragma unroll
                    for (int h = 0; h < 5; ++h)
                        *(u32*)(smem + h*PLANE + r*ROWB + cp*4) = packh(gA[h], gB[h]);
                }
            }
        }
        __syncthreads();
    }

    // ==== blo table (overlays raw buffer): entry (s,lane) = 16B, both nt ====
    for (int u = tid; u < 160; u += NTHR) {
        int el = u & 31, s = u >> 5;
        int egrp = el >> 2, etg = el & 3;
        u32 e[4];
        #pragma unroll
        for (int nt = 0; nt < 2; ++nt) {
            int co = nt*8 + egrp;
            #pragma unroll
            for (int j = 0; j < 2; ++j) {
                int ci = etg*2 + j*8;
                float w0 = __ldg(W + (co*16 + ci    )*5 + s);
                float w1 = __ldg(W + (co*16 + ci + 1)*5 + s);
                e[nt*2+j] = packh(w0 - __half2float(__float2half(w0)),
                                  w1 - __half2float(__float2half(w1)));
            }
        }
        asm volatile("st.shared.v4.b32 [%0], {%1,%2,%3,%4};"
            :: "r"(sbase + OFF_RAW + (u32)u*16), "r"(e[0]), "r"(e[1]), "r"(e[2]), "r"(e[3])
            : "memory");
    }

    // ==== bhi fragments in registers (h-invariant) ====
    u32 bhi[5][2][2];
    #pragma unroll
    for (int s = 0; s < 5; ++s)
        #pragma unroll
        for (int nt = 0; nt < 2; ++nt)
            #pragma unroll
            for (int j = 0; j < 2; ++j) {
                int co = nt*8 + grp;
                int ci = tg*2 + j*8;
                float w0 = __ldg(W + (co*16 + ci    )*5 + s);
                float w1 = __ldg(W + (co*16 + ci + 1)*5 + s);
                bhi[s][nt][j] = (u32)__half_as_ushort(__float2half(w0))
                              | ((u32)__half_as_ushort(__float2half(w1)) << 16);
            }
    __syncthreads();

    // ==== mma phase: 4 warps x 32 rows ====
    const int matid = lane >> 3, r8 = lane & 7;
    const u32 laneoff = (u32)((r8 + ((matid & 1) << 3)) * ROWB + ((matid >> 1) << 4));
    const u32 am0 = sbase + (u32)(wid*32)*ROWB + laneoff;
    const u32 am1 = am0 + 16*ROWB;
    const u32 bbase = sbase + OFF_RAW + (u32)lane*16;

    float bias0 = __ldg(b + tg*2), bias1 = __ldg(b + tg*2 + 1);
    float bias2 = __ldg(b + 8 + tg*2), bias3 = __ldg(b + 8 + tg*2 + 1);

    #pragma unroll 1
    for (int h = 0; h < 5; ++h) {
        float acc[2][2][4];                       // [m][nt][c]
        #pragma unroll
        for (int m = 0; m < 2; ++m) {
            acc[m][0][0]=bias0; acc[m][0][1]=bias1; acc[m][0][2]=bias0; acc[m][0][3]=bias1;
            acc[m][1][0]=bias2; acc[m][1][1]=bias3; acc[m][1][2]=bias2; acc[m][1][3]=bias3;
        }
        const u32 hb = (u32)(h*PLANE);

        #pragma unroll
        for (int s = 0; s < 5; ++s) {
            u32 a0[4], a1[4], el[4];
            ldmx4(a0, am0 + hb + (u32)s*ROWB);
            ldmx4(a1, am1 + hb + (u32)s*ROWB);
            lds128(el, bbase + (u32)s*512);
            mma16816(acc[0][0], a0, bhi[s][0][0], bhi[s][0][1]);   // hi
            mma16816(acc[0][1], a0, bhi[s][1][0], bhi[s][1][1]);
            mma16816(acc[1][0], a1, bhi[s][0][0], bhi[s][0][1]);
            mma16816(acc[1][1], a1, bhi[s][1][0], bhi[s][1][1]);
            mma16816(acc[0][0], a0, el[0], el[1]);                 // lo
            mma16816(acc[0][1], a0, el[2], el[3]);
            mma16816(acc[1][0], a1, el[0], el[1]);
            mma16816(acc[1][1], a1, el[2], el[3]);
        }

        // ---- store ----
        #pragma unroll
        for (int m = 0; m < 2; ++m) {
            const int fr = f0 + wid*32 + m*16 + grp;
            #pragma unroll
            for (int nt = 0; nt < 2; ++nt) {
                const int co0 = nt*8 + tg*2;
                float* y0 = y + ((size_t)((n*16 + co0)*5 + h))*FO;
                float* y1 = y0 + (size_t)5*FO;
                if (fr < FO)     { y0[fr]   = acc[m][nt][0];  y1[fr]   = acc[m][nt][1]; }
                if (fr + 8 < FO) { y0[fr+8] = acc[m][nt][2];  y1[fr+8] = acc[m][nt][3]; }
            }
        }
    }
}

extern "C" void kernel_launch(void* const* d_in, const int* in_sizes, int n_in,
                              void* d_out, int out_size)
{
    (void)in_sizes; (void)n_in; (void)out_size;
    const float* x = (const float*)d_in[0];
    const float* W = (const float*)d_in[1];
    const float* b = (const float*)d_in[2];
    float*       y = (float*)d_out;

    cudaFuncSetAttribute(meshconv_mma,
                         cudaFuncAttributeMaxDynamicSharedMemorySize, SMEM_BYTES);

    dim3 grid(NTILES, 4);
    meshconv_mma<<<grid, NTHR, SMEM_BYTES>>>(x, W, b, y);
}

// round 17
// speedup vs baseline: 1.0925x; 1.0925x over previous
#include <cuda_runtime.h>
#include <cuda_fp16.h>
#include <cstdint>

// MeshConv via mma.sync (HMMA) fp16, split on B (W = Whi + Wlo), A = fp16(g).
// R16 = R13 (best, 303us) + IDIV-free warp-per-plane staging (the good half of
// R15). The B-register restructure of R15 is reverted: B frags come from smem
// as two transient LDS.128 per (h,s) — short live ranges schedule better.

#define F_DIM  500000
#define FO     499996
#define TILE_F 128
#define NTILES 3907
#define NTHR   128
#define GR     132
#define ROWB   48                 // gpack row bytes (8 ci-pair words + pad)
#define PLANE  (GR*ROWB)          // 6336 B per h
#define OFF_RAW (5*PLANE)         // 31680: raw x staging / B table overlay
#define RAWSTR 2656               // raw plane stride (2640 + 16 pad)
#define SMEM_BYTES (OFF_RAW + 4*RAWSTR)   // 42304

typedef unsigned int u32;

__device__ __forceinline__ void mma16816(float* c, const u32* a, u32 b0, u32 b1) {
    asm volatile("mma.sync.aligned.m16n8k16.row.col.f32.f16.f16.f32 "
        "{%0,%1,%2,%3}, {%4,%5,%6,%7}, {%8,%9}, {%0,%1,%2,%3};"
        : "+f"(c[0]), "+f"(c[1]), "+f"(c[2]), "+f"(c[3])
        : "r"(a[0]), "r"(a[1]), "r"(a[2]), "r"(a[3]), "r"(b0), "r"(b1));
}
__device__ __forceinline__ void ldmx4(u32* r, u32 addr) {
    asm volatile("ldmatrix.sync.aligned.m8n8.x4.shared.b16 {%0,%1,%2,%3}, [%4];"
        : "=r"(r[0]), "=r"(r[1]), "=r"(r[2]), "=r"(r[3]) : "r"(addr));
}
__device__ __forceinline__ void lds128(u32* r, u32 addr) {
    asm volatile("ld.shared.v4.b32 {%0,%1,%2,%3}, [%4];"
        : "=r"(r[0]), "=r"(r[1]), "=r"(r[2]), "=r"(r[3]) : "r"(addr));
}
__device__ __forceinline__ u32 packh(float a, float bq) {   // {lo=a, hi=bq}
    return (u32)__half_as_ushort(__float2half(a))
         | ((u32)__half_as_ushort(__float2half(bq)) << 16);
}

extern __shared__ unsigned char smem[];

__global__ __launch_bounds__(NTHR, 5)
void meshconv_mma(const float* __restrict__ x, const float* __restrict__ W,
                  const float* __restrict__ b, float* __restrict__ y)
{
    const int tid  = threadIdx.x;
    const int wid  = tid >> 5, lane = tid & 31;
    const int grp  = lane >> 2, tg = lane & 3;
    const int n    = blockIdx.y;
    const int f0   = blockIdx.x * TILE_F;
    const u32 sbase = (u32)__cvta_generic_to_shared(smem);

    // valid bytes in a 2640B ci-slice starting at f0 (tail zero-filled)
    long long vbl = ((long long)F_DIM - f0) * 20;
    int vb = vbl > GR*20 ? GR*20 : (int)vbl;

    const char* xb = (const char*)x;

    // ==== staging + gpack build, 4 chunks of 4 ci planes (warp-per-plane) ====
    for (int c = 0; c < 4; ++c) {
        // coalesced 16B cp.async: warp wid stages plane wid of this chunk
        {
            const char* src0 = xb + ((size_t)(n*16 + 4*c + wid))*F_DIM*20 + (size_t)f0*20;
            u32 dst0 = sbase + OFF_RAW + wid*RAWSTR;
            #pragma unroll
            for (int j = 0; j < 6; ++j) {
                int i = lane + 32*j;
                if (i < 165) {
                    int ob = i * 16;
                    int sz = vb - ob; sz = sz < 0 ? 0 : (sz > 16 ? 16 : sz);
                    asm volatile("cp.async.ca.shared.global [%0], [%1], 16, %2;"
                                 :: "r"(dst0 + ob), "l"(src0 + (sz ? ob : 0)), "r"(sz)
                                 : "memory");
                }
            }
        }
        asm volatile("cp.async.commit_group;" ::: "memory");
        asm volatile("cp.async.wait_group 0;" ::: "memory");
        __syncthreads();

        // g-compute: thread = (r, ci-pair within chunk); bank-perfect raw LDS
        {
            const int rl = lane & 15, cpl = lane >> 4;
            const int cp = 2*c + cpl;
            for (int rb = wid*16; rb < GR; rb += 64) {
                int r = rb + rl;
                if (r < GR) {
                    const float* pa = (const float*)(smem + OFF_RAW + (2*cpl  )*RAWSTR + r*20);
                    const float* pb = (const float*)(smem + OFF_RAW + (2*cpl+1)*RAWSTR + r*20);
                    float a0=pa[0], a1=pa[1], a2=pa[2], a3=pa[3], a4=pa[4];
                    float c0=pb[0], c1=pb[1], c2=pb[2], c3=pb[3], c4=pb[4];
                    float gA[5], gB[5];
                    gA[0]=a0; gA[1]=a1+a3; gA[2]=a2+a4; gA[3]=fabsf(a1-a3); gA[4]=fabsf(a2-a4);
                    gB[0]=c0; gB[1]=c1+c3; gB[2]=c2+c4; gB[3]=fabsf(c1-c3); gB[4]=fabsf(c2-c4);
                    #pragma unroll
                    for (int h = 0; h < 5; ++h)
                        *(u32*)(smem + h*PLANE + r*ROWB + cp*4) = packh(gA[h], gB[h]);
                }
            }
        }
        __syncthreads();
    }

    // ==== B table (overlays raw buffer): entry (s,nt,lane) = {bhi0,bhi1,blo0,blo1} ====
    for (int u = tid; u < 320; u += NTHR) {
        int el = u & 31, nt = (u >> 5) & 1, s = u >> 6;
        int egrp = el >> 2, etg = el & 3;
        int co = nt*8 + egrp;
        u32 e[4];
        #pragma unroll
        for (int j = 0; j < 2; ++j) {
            int ci = etg*2 + j*8;
            float w0 = __ldg(W + (co*16 + ci    )*5 + s);
            float w1 = __ldg(W + (co*16 + ci + 1)*5 + s);
            __half h0 = __float2half(w0), h1 = __float2half(w1);
            e[j]   = (u32)__half_as_ushort(h0) | ((u32)__half_as_ushort(h1) << 16);
            e[2+j] = packh(w0 - __half2float(h0), w1 - __half2float(h1));
        }
        asm volatile("st.shared.v4.b32 [%0], {%1,%2,%3,%4};"
            :: "r"(sbase + OFF_RAW + (u32)u*16), "r"(e[0]), "r"(e[1]), "r"(e[2]), "r"(e[3])
            : "memory");
    }
    __syncthreads();

    // ==== mma phase: 4 warps x 32 rows ====
    const int matid = lane >> 3, r8 = lane & 7;
    const u32 laneoff = (u32)((r8 + ((matid & 1) << 3)) * ROWB + ((matid >> 1) << 4));
    const u32 am0 = sbase + (u32)(wid*32)*ROWB + laneoff;
    const u32 am1 = am0 + 16*ROWB;
    const u32 bbase = sbase + OFF_RAW + (u32)lane*16;

    float bias0 = __ldg(b + tg*2), bias1 = __ldg(b + tg*2 + 1);
    float bias2 = __ldg(b + 8 + tg*2), bias3 = __ldg(b + 8 + tg*2 + 1);

    #pragma unroll 1
    for (int h = 0; h < 5; ++h) {
        float acc[2][2][4];                       // [m][nt][c]
        #pragma unroll
        for (int m = 0; m < 2; ++m) {
            acc[m][0][0]=bias0; acc[m][0][1]=bias1; acc[m][0][2]=bias0; acc[m][0][3]=bias1;
            acc[m][1][0]=bias2; acc[m][1][1]=bias3; acc[m][1][2]=bias2; acc[m][1][3]=bias3;
        }
        const u32 hb = (u32)(h*PLANE);

        #pragma unroll
        for (int s = 0; s < 5; ++s) {
            u32 a0[4], a1[4], e0[4], e1[4];
            ldmx4(a0, am0 + hb + (u32)s*ROWB);
            ldmx4(a1, am1 + hb + (u32)s*ROWB);
            lds128(e0, bbase + (u32)(s*2    )*512);
            lds128(e1, bbase + (u32)(s*2 + 1)*512);
            mma16816(acc[0][0], a0, e0[0], e0[1]);   // hi
            mma16816(acc[0][1], a0, e1[0], e1[1]);
            mma16816(acc[1][0], a1, e0[0], e0[1]);
            mma16816(acc[1][1], a1, e1[0], e1[1]);
            mma16816(acc[0][0], a0, e0[2], e0[3]);   // lo
            mma16816(acc[0][1], a0, e1[2], e1[3]);
            mma16816(acc[1][0], a1, e0[2], e0[3]);
            mma16816(acc[1][1], a1, e1[2], e1[3]);
        }

        // ---- store ----
        #pragma unroll
        for (int m = 0; m < 2; ++m) {
            const int fr = f0 + wid*32 + m*16 + grp;
            #pragma unroll
            for (int nt = 0; nt < 2; ++nt) {
                const int co0 = nt*8 + tg*2;
                float* y0 = y + ((size_t)((n*16 + co0)*5 + h))*FO;
                float* y1 = y0 + (size_t)5*FO;
                if (fr < FO)     { y0[fr]   = acc[m][nt][0];  y1[fr]   = acc[m][nt][1]; }
                if (fr + 8 < FO) { y0[fr+8] = acc[m][nt][2];  y1[fr+8] = acc[m][nt][3]; }
            }
        }
    }
}

extern "C" void kernel_launch(void* const* d_in, const int* in_sizes, int n_in,
                              void* d_out, int out_size)
{
    (void)in_sizes; (void)n_in; (void)out_size;
    const float* x = (const float*)d_in[0];
    const float* W = (const float*)d_in[1];
    const float* b = (const float*)d_in[2];
    float*       y = (float*)d_out;

    cudaFuncSetAttribute(meshconv_mma,
                         cudaFuncAttributeMaxDynamicSharedMemorySize, SMEM_BYTES);

    dim3 grid(NTILES, 4);
    meshconv_mma<<<grid, NTHR, SMEM_BYTES>>>(x, W, b, y);
}